// round 6
// baseline (speedup 1.0000x reference)
#include <cuda_runtime.h>

// ---------------------------------------------------------------------------
// PAFA loss, reduced to scalars:
//   S        = sum_i ||x_i||^2
//   s_p      = segment sum of features for patient p,  n_p = count
//   within   = S - sum_p ||s_p||^2 / n_p
//   sumsq_c  = sum_p ||s_p||^2 / n_p^2          (= sum_p ||c_p||^2)
//   total[d] = sum_p s_p[d] / n_p               (= sum_p c_p)
//   between  = P*sumsq_c - ||total||^2
//   gpal     = sumsq_c/P - ||total||^2 / P^2
//   loss     = 0.1*within/(between+1e-6) + 0.1*gpal
//
// Pipeline (no heavy atomics; feature matrix read exactly once, coalesced):
//   K0 init+dtype-detect -> K1 histogram -> K2 block scan -> K3 scatter perm
//   -> K4 per-patient gather-sum (the HBM-bound pass) -> K5 finalize
// ---------------------------------------------------------------------------

#define PMAX 4096
#define NMAX (1 << 20)
#define DMAX 1024
#define CURPAD 32   // one cursor per 128B L2 line to kill atomic line-contention

__device__ int   g_counts[PMAX];
__device__ int   g_offsets[PMAX];
__device__ int   g_cursors[PMAX * CURPAD];
__device__ int   g_perm[NMAX];
__device__ float g_total[DMAX];
__device__ float g_scalars[3];   // [0]=S, [1]=sum ||s||^2/n, [2]=sum ||s||^2/n^2
__device__ int   g_idstride;
__device__ int   g_idflag;

// ---------------------------------------------------------------------------
// K0: zero scratch; detect whether patient_ids are int64 (stride 2 in int32
// words) or int32 (stride 1). For int64 LE with ids in [0,P), all odd 32-bit
// words are 0; for int32, 256 random odd-position ids being all-zero is
// vanishingly unlikely.
// ---------------------------------------------------------------------------
__global__ void k_init(const int* __restrict__ ids32, int N) {
    int t = threadIdx.x;
    if (t == 0) g_idflag = 0;
    for (int i = t; i < PMAX; i += blockDim.x) g_counts[i] = 0;
    for (int i = t; i < DMAX; i += blockDim.x) g_total[i] = 0.0f;
    if (t < 3) g_scalars[t] = 0.0f;
    __syncthreads();
    if (t < 256) {
        int idx = 2 * t + 1;
        if (idx < N) {                // safe for both layouts (>= N words)
            if (ids32[idx] != 0) atomicOr(&g_idflag, 1);
        }
    }
    __syncthreads();
    if (t == 0) g_idstride = g_idflag ? 1 : 2;
}

// ---------------------------------------------------------------------------
// K1: histogram of patient ids via shared-memory aggregation.
// ---------------------------------------------------------------------------
__global__ void k_hist(const int* __restrict__ ids32, int N,
                       const int* __restrict__ pptr) {
    __shared__ int sh[PMAX];
    int P = *pptr;
    if (P > PMAX) P = PMAX;
    int stride = g_idstride;
    for (int i = threadIdx.x; i < P; i += blockDim.x) sh[i] = 0;
    __syncthreads();
    for (int i = blockIdx.x * blockDim.x + threadIdx.x; i < N;
         i += gridDim.x * blockDim.x) {
        int id = ids32[(size_t)i * stride];
        if (id >= 0 && id < P) atomicAdd(&sh[id], 1);
    }
    __syncthreads();
    for (int i = threadIdx.x; i < P; i += blockDim.x)
        if (sh[i]) atomicAdd(&g_counts[i], sh[i]);
}

// ---------------------------------------------------------------------------
// K2: exclusive scan of g_counts[0..PMAX) -> g_offsets + padded g_cursors.
// One block of 1024 threads, 4 elements each (covers PMAX exactly).
// ---------------------------------------------------------------------------
__global__ void k_scan() {
    __shared__ int warpsum[32];
    int t = threadIdx.x;
    int c0 = g_counts[4 * t + 0];
    int c1 = g_counts[4 * t + 1];
    int c2 = g_counts[4 * t + 2];
    int c3 = g_counts[4 * t + 3];
    int s0 = c0, s1 = s0 + c1, s2 = s1 + c2, s3 = s2 + c3;  // local inclusive
    int lane = t & 31, w = t >> 5;
    int v = s3;
    #pragma unroll
    for (int o = 1; o < 32; o <<= 1) {
        int u = __shfl_up_sync(0xffffffffu, v, o);
        if (lane >= o) v += u;
    }
    if (lane == 31) warpsum[w] = v;
    __syncthreads();
    if (w == 0) {
        int ws = warpsum[lane];
        #pragma unroll
        for (int o = 1; o < 32; o <<= 1) {
            int u = __shfl_up_sync(0xffffffffu, ws, o);
            if (lane >= o) ws += u;
        }
        warpsum[lane] = ws;
    }
    __syncthreads();
    int base = (w > 0 ? warpsum[w - 1] : 0) + (v - s3);  // exclusive thread base
    g_offsets[4 * t + 0] = base;
    g_offsets[4 * t + 1] = base + s0;
    g_offsets[4 * t + 2] = base + s1;
    g_offsets[4 * t + 3] = base + s2;
    g_cursors[(4 * t + 0) * CURPAD] = base;
    g_cursors[(4 * t + 1) * CURPAD] = base + s0;
    g_cursors[(4 * t + 2) * CURPAD] = base + s1;
    g_cursors[(4 * t + 3) * CURPAD] = base + s2;
}

// ---------------------------------------------------------------------------
// K3: scatter row indices into patient-contiguous order. Cursors padded to
// one per 128B line so contended atomics don't share L2 lines.
// ---------------------------------------------------------------------------
__global__ void k_scatter(const int* __restrict__ ids32, int N,
                          const int* __restrict__ pptr) {
    int P = *pptr;
    if (P > PMAX) P = PMAX;
    int stride = g_idstride;
    for (int i = blockIdx.x * blockDim.x + threadIdx.x; i < N;
         i += gridDim.x * blockDim.x) {
        int id = ids32[(size_t)i * stride];
        if (id >= 0 && id < P) {
            int pos = atomicAdd(&g_cursors[id * CURPAD], 1);
            g_perm[pos] = i;
        }
    }
}

// ---------------------------------------------------------------------------
// K4: per-patient gather-and-sum. One block per patient (persistent loop).
// blockDim = 256. Each row is D floats = D/4 float4 chunks; threads are
// grouped so one group of (D/4) lanes covers one row, groups iterate rows.
// Reads features exactly once (streaming loads, no cache pollution),
// coalesced 1KB rows. No global atomics on the hot path; per-patient flush
// is P*D light atomics total.
// ---------------------------------------------------------------------------
__global__ void k_patient(const float* __restrict__ feat, int D,
                          const int* __restrict__ pptr) {
    __shared__ int   shperm[1024];
    __shared__ float shsum[DMAX];
    __shared__ float wred[8];
    __shared__ float shsq;

    int P = *pptr;
    if (P > PMAX) P = PMAX;
    int cpd    = D >> 2;                 // float4 chunks per row
    int groups = blockDim.x / cpd;       // rows processed in parallel
    int gid    = threadIdx.x / cpd;
    int lane   = threadIdx.x % cpd;
    bool active = (gid < groups);

    for (int p = blockIdx.x; p < P; p += gridDim.x) {
        int rows = g_counts[p];
        int base = g_offsets[p];

        for (int i = threadIdx.x; i < D; i += blockDim.x) shsum[i] = 0.0f;
        if (threadIdx.x == 0) shsq = 0.0f;
        __syncthreads();

        float4 acc = make_float4(0.f, 0.f, 0.f, 0.f);
        float  sq  = 0.0f;

        for (int cs = 0; cs < rows; cs += 1024) {
            int cr = rows - cs; if (cr > 1024) cr = 1024;
            for (int j = threadIdx.x; j < cr; j += blockDim.x)
                shperm[j] = __ldcs(&g_perm[base + cs + j]);
            __syncthreads();
            if (active) {
                #pragma unroll 4
                for (int j = gid; j < cr; j += groups) {
                    int row = shperm[j];
                    float4 v = __ldcs(reinterpret_cast<const float4*>(
                                          feat + (size_t)row * D) + lane);
                    acc.x += v.x; acc.y += v.y; acc.z += v.z; acc.w += v.w;
                    sq = fmaf(v.x, v.x, sq);
                    sq = fmaf(v.y, v.y, sq);
                    sq = fmaf(v.z, v.z, sq);
                    sq = fmaf(v.w, v.w, sq);
                }
            }
            __syncthreads();
        }

        // Flush per-thread accumulators into shared per-column sums.
        if (active) {
            atomicAdd(&shsum[lane * 4 + 0], acc.x);
            atomicAdd(&shsum[lane * 4 + 1], acc.y);
            atomicAdd(&shsum[lane * 4 + 2], acc.z);
            atomicAdd(&shsum[lane * 4 + 3], acc.w);
        }
        // Reduce the squared-norm contribution (counts toward S).
        #pragma unroll
        for (int o = 16; o > 0; o >>= 1)
            sq += __shfl_down_sync(0xffffffffu, sq, o);
        if ((threadIdx.x & 31) == 0) atomicAdd(&shsq, sq);
        __syncthreads();

        // Per-patient scalar outputs.
        float n = (float)rows; if (n < 1.0f) n = 1.0f;
        float ssq_part = 0.0f;
        for (int t = threadIdx.x; t < D; t += blockDim.x) {
            float s = shsum[t];
            atomicAdd(&g_total[t], s / n);
            ssq_part = fmaf(s, s, ssq_part);
        }
        #pragma unroll
        for (int o = 16; o > 0; o >>= 1)
            ssq_part += __shfl_down_sync(0xffffffffu, ssq_part, o);
        if ((threadIdx.x & 31) == 0) wred[threadIdx.x >> 5] = ssq_part;
        __syncthreads();
        if (threadIdx.x == 0) {
            float ssq = 0.0f;
            int nw = blockDim.x >> 5;
            for (int i = 0; i < nw; i++) ssq += wred[i];
            atomicAdd(&g_scalars[0], shsq);
            atomicAdd(&g_scalars[1], ssq / n);
            atomicAdd(&g_scalars[2], ssq / (n * n));
        }
        __syncthreads();   // shared reuse across persistent iterations
    }
}

// ---------------------------------------------------------------------------
// K5: finalize -> scalar loss.
// ---------------------------------------------------------------------------
__global__ void k_final(float* __restrict__ out, int D,
                        const int* __restrict__ pptr) {
    __shared__ float wred[8];
    float part = 0.0f;
    for (int t = threadIdx.x; t < D; t += blockDim.x) {
        float v = g_total[t];
        part = fmaf(v, v, part);
    }
    #pragma unroll
    for (int o = 16; o > 0; o >>= 1)
        part += __shfl_down_sync(0xffffffffu, part, o);
    if ((threadIdx.x & 31) == 0) wred[threadIdx.x >> 5] = part;
    __syncthreads();
    if (threadIdx.x == 0) {
        float T2 = 0.0f;
        int nw = blockDim.x >> 5;
        for (int i = 0; i < nw; i++) T2 += wred[i];
        float Pf = (float)(*pptr);
        float S   = g_scalars[0];
        float son = g_scalars[1];
        float sc  = g_scalars[2];
        float within  = S - son;
        float between = Pf * sc - T2;
        float gpal    = sc / Pf - T2 / (Pf * Pf);
        out[0] = 0.1f * within / (between + 1e-6f) + 0.1f * gpal;
    }
}

// ---------------------------------------------------------------------------
extern "C" void kernel_launch(void* const* d_in, const int* in_sizes, int n_in,
                              void* d_out, int out_size) {
    const float* feat  = (const float*)d_in[0];
    const int*   ids32 = (const int*)d_in[1];   // stride-detected on device
    const int*   pptr  = (const int*)d_in[2];   // low 32 bits of num_patients
    (void)n_in; (void)out_size;

    int N = in_sizes[1];
    int D = in_sizes[0] / N;

    k_init<<<1, 1024>>>(ids32, N);
    k_hist<<<296, 256>>>(ids32, N, pptr);
    k_scan<<<1, 1024>>>();
    k_scatter<<<296, 256>>>(ids32, N, pptr);
    k_patient<<<512, 256>>>(feat, D, pptr);
    k_final<<<1, 256>>>((float*)d_out, D, pptr);
}

// round 16
// speedup vs baseline: 1.1920x; 1.1920x over previous
#include <cuda_runtime.h>

// ---------------------------------------------------------------------------
// PAFA loss, reduced to scalars:
//   S        = sum_i ||x_i||^2
//   s_p      = segment sum of features for patient p,  n_p = count
//   within   = S - sum_p ||s_p||^2 / n_p
//   sumsq_c  = sum_p ||s_p||^2 / n_p^2          (= sum_p ||c_p||^2)
//   total[d] = sum_p s_p[d] / n_p               (= sum_p c_p)
//   between  = P*sumsq_c - ||total||^2
//   gpal     = sumsq_c/P - ||total||^2 / P^2
//   loss     = 0.1*within/(between+1e-6) + 0.1*gpal
//
// Pipeline:
//   K0 init+dtype-detect -> K1 histogram -> K2 block scan -> K3 scatter perm
//   -> K4 gather partial sums (HBM-bound, 4 blocks/patient, reg accumulators,
//      atomic flush to g_sums) -> K5 centroid scalars -> K6 finalize
// ---------------------------------------------------------------------------

#define PMAX 4096
#define NMAX (1 << 20)
#define DMAX 1024
#define CURPAD 32   // one cursor per 128B L2 line to kill atomic line-contention
#define SPLIT 4     // blocks per patient in K4
#define TPB4 128    // threads per block in K4

__device__ int   g_counts[PMAX];
__device__ int   g_offsets[PMAX];
__device__ int   g_cursors[PMAX * CURPAD];
__device__ int   g_perm[NMAX];
__device__ float g_sums[(size_t)PMAX * 512];  // per-patient segment sums (D<=512)
__device__ float g_total[DMAX];
__device__ float g_scalars[3];   // [0]=S, [1]=sum ||s||^2/n, [2]=sum ||s||^2/n^2
__device__ int   g_idstride;
__device__ int   g_idflag;

// ---------------------------------------------------------------------------
// K0: zero scratch; block 0 additionally detects whether patient_ids are
// int64 (stride 2 in int32 words) or int32 (stride 1). For int64 LE with ids
// in [0,P), all odd 32-bit words are 0.
// ---------------------------------------------------------------------------
__global__ void k_init(const int* __restrict__ ids32, int N, int D,
                       const int* __restrict__ pptr) {
    int P = *pptr;
    if (P > PMAX) P = PMAX;
    size_t sums_n = (size_t)P * D;
    int gtid = blockIdx.x * blockDim.x + threadIdx.x;
    int gsz  = gridDim.x * blockDim.x;
    for (size_t i = gtid; i < sums_n; i += gsz) g_sums[i] = 0.0f;
    for (int i = gtid; i < PMAX; i += gsz) g_counts[i] = 0;
    for (int i = gtid; i < DMAX; i += gsz) g_total[i] = 0.0f;
    if (gtid < 3) g_scalars[gtid] = 0.0f;

    if (blockIdx.x == 0) {
        int t = threadIdx.x;
        if (t == 0) g_idflag = 0;
        __syncthreads();
        if (t < 256) {
            int idx = 2 * t + 1;
            if (idx < N) {            // safe for both layouts (>= N words)
                if (ids32[idx] != 0) atomicOr(&g_idflag, 1);
            }
        }
        __syncthreads();
        if (t == 0) g_idstride = g_idflag ? 1 : 2;
    }
}

// ---------------------------------------------------------------------------
// K1: histogram of patient ids via shared-memory aggregation.
// ---------------------------------------------------------------------------
__global__ void k_hist(const int* __restrict__ ids32, int N,
                       const int* __restrict__ pptr) {
    __shared__ int sh[PMAX];
    int P = *pptr;
    if (P > PMAX) P = PMAX;
    int stride = g_idstride;
    for (int i = threadIdx.x; i < P; i += blockDim.x) sh[i] = 0;
    __syncthreads();
    for (int i = blockIdx.x * blockDim.x + threadIdx.x; i < N;
         i += gridDim.x * blockDim.x) {
        int id = ids32[(size_t)i * stride];
        if (id >= 0 && id < P) atomicAdd(&sh[id], 1);
    }
    __syncthreads();
    for (int i = threadIdx.x; i < P; i += blockDim.x)
        if (sh[i]) atomicAdd(&g_counts[i], sh[i]);
}

// ---------------------------------------------------------------------------
// K2: exclusive scan of g_counts[0..PMAX) -> g_offsets + padded g_cursors.
// One block of 1024 threads, 4 elements each (covers PMAX exactly).
// ---------------------------------------------------------------------------
__global__ void k_scan() {
    __shared__ int warpsum[32];
    int t = threadIdx.x;
    int c0 = g_counts[4 * t + 0];
    int c1 = g_counts[4 * t + 1];
    int c2 = g_counts[4 * t + 2];
    int c3 = g_counts[4 * t + 3];
    int s0 = c0, s1 = s0 + c1, s2 = s1 + c2, s3 = s2 + c3;  // local inclusive
    int lane = t & 31, w = t >> 5;
    int v = s3;
    #pragma unroll
    for (int o = 1; o < 32; o <<= 1) {
        int u = __shfl_up_sync(0xffffffffu, v, o);
        if (lane >= o) v += u;
    }
    if (lane == 31) warpsum[w] = v;
    __syncthreads();
    if (w == 0) {
        int ws = warpsum[lane];
        #pragma unroll
        for (int o = 1; o < 32; o <<= 1) {
            int u = __shfl_up_sync(0xffffffffu, ws, o);
            if (lane >= o) ws += u;
        }
        warpsum[lane] = ws;
    }
    __syncthreads();
    int base = (w > 0 ? warpsum[w - 1] : 0) + (v - s3);  // exclusive thread base
    g_offsets[4 * t + 0] = base;
    g_offsets[4 * t + 1] = base + s0;
    g_offsets[4 * t + 2] = base + s1;
    g_offsets[4 * t + 3] = base + s2;
    g_cursors[(4 * t + 0) * CURPAD] = base;
    g_cursors[(4 * t + 1) * CURPAD] = base + s0;
    g_cursors[(4 * t + 2) * CURPAD] = base + s1;
    g_cursors[(4 * t + 3) * CURPAD] = base + s2;
}

// ---------------------------------------------------------------------------
// K3: scatter row indices into patient-contiguous order. Cursors padded to
// one per 128B line. Grid sized so each thread does ~1 element (TLP hides the
// ~318cyc ATOMG round-trip; round-6 profile showed occ 22% / issue 2.7%).
// ---------------------------------------------------------------------------
__global__ void k_scatter(const int* __restrict__ ids32, int N,
                          const int* __restrict__ pptr) {
    int P = *pptr;
    if (P > PMAX) P = PMAX;
    int stride = g_idstride;
    for (int i = blockIdx.x * blockDim.x + threadIdx.x; i < N;
         i += gridDim.x * blockDim.x) {
        int id = ids32[(size_t)i * stride];
        if (id >= 0 && id < P) {
            int pos = atomicAdd(&g_cursors[id * CURPAD], 1);
            g_perm[pos] = i;
        }
    }
}

// ---------------------------------------------------------------------------
// K4: gather partial sums. SPLIT blocks per patient; block b handles patient
// b/SPLIT, row-part b%SPLIT. 128 threads; D/4 float4 lanes per row, groups =
// 128/(D/4) rows in parallel. Register accumulators only; flush = 4 atomic
// floats per thread into g_sums (per-address collision count = SPLIT).
// Reads features exactly once, streaming, coalesced 1KB rows.
// ---------------------------------------------------------------------------
__global__ void k_patient(const float* __restrict__ feat, int D,
                          const int* __restrict__ pptr) {
    __shared__ int   shperm[512];
    __shared__ float wred[TPB4 / 32];

    int P = *pptr;
    if (P > PMAX) P = PMAX;
    int p    = blockIdx.x / SPLIT;
    int part = blockIdx.x % SPLIT;
    if (p >= P) return;

    int rows = g_counts[p];
    int base = g_offsets[p];
    int r0 = (int)(((long long)rows * part) / SPLIT);
    int r1 = (int)(((long long)rows * (part + 1)) / SPLIT);
    int myrows = r1 - r0;
    int mybase = base + r0;

    int cpd    = D >> 2;                 // float4 chunks per row
    int groups = TPB4 / cpd;             // rows in parallel (>=1 for D<=512)
    int gid    = threadIdx.x / cpd;
    int lane   = threadIdx.x % cpd;
    bool active = (gid < groups);

    float4 acc = make_float4(0.f, 0.f, 0.f, 0.f);
    float  sq  = 0.0f;

    for (int cs = 0; cs < myrows; cs += 512) {
        int cr = myrows - cs; if (cr > 512) cr = 512;
        for (int j = threadIdx.x; j < cr; j += TPB4)
            shperm[j] = g_perm[mybase + cs + j];
        __syncthreads();
        if (active) {
            #pragma unroll 4
            for (int j = gid; j < cr; j += groups) {
                int row = shperm[j];
                float4 v = __ldcs(reinterpret_cast<const float4*>(
                                      feat + (size_t)row * D) + lane);
                acc.x += v.x; acc.y += v.y; acc.z += v.z; acc.w += v.w;
                sq = fmaf(v.x, v.x, sq);
                sq = fmaf(v.y, v.y, sq);
                sq = fmaf(v.z, v.z, sq);
                sq = fmaf(v.w, v.w, sq);
            }
        }
        __syncthreads();
    }

    if (active) {
        float* s = &g_sums[(size_t)p * D + lane * 4];
        atomicAdd(s + 0, acc.x);
        atomicAdd(s + 1, acc.y);
        atomicAdd(s + 2, acc.z);
        atomicAdd(s + 3, acc.w);
    }
    #pragma unroll
    for (int o = 16; o > 0; o >>= 1)
        sq += __shfl_down_sync(0xffffffffu, sq, o);
    if ((threadIdx.x & 31) == 0) wred[threadIdx.x >> 5] = sq;
    __syncthreads();
    if (threadIdx.x == 0) {
        float s = 0.0f;
        #pragma unroll
        for (int i = 0; i < TPB4 / 32; i++) s += wred[i];
        atomicAdd(&g_scalars[0], s);
    }
}

// ---------------------------------------------------------------------------
// K5: per-patient centroid scalars from g_sums. One block per patient.
// ---------------------------------------------------------------------------
__global__ void k_centroid(int D, const int* __restrict__ pptr) {
    __shared__ float wred[8];
    int P = *pptr;
    if (P > PMAX) P = PMAX;
    int p = blockIdx.x;
    if (p >= P) return;

    int rows = g_counts[p];
    float n = (float)rows; if (n < 1.0f) n = 1.0f;
    float inv_n = 1.0f / n;

    float ssq = 0.0f;
    for (int d = threadIdx.x; d < D; d += blockDim.x) {
        float s = g_sums[(size_t)p * D + d];
        atomicAdd(&g_total[d], s * inv_n);
        ssq = fmaf(s, s, ssq);
    }
    #pragma unroll
    for (int o = 16; o > 0; o >>= 1)
        ssq += __shfl_down_sync(0xffffffffu, ssq, o);
    if ((threadIdx.x & 31) == 0) wred[threadIdx.x >> 5] = ssq;
    __syncthreads();
    if (threadIdx.x == 0) {
        float t = 0.0f;
        int nw = blockDim.x >> 5;
        for (int i = 0; i < nw; i++) t += wred[i];
        atomicAdd(&g_scalars[1], t * inv_n);
        atomicAdd(&g_scalars[2], t * inv_n * inv_n);
    }
}

// ---------------------------------------------------------------------------
// K6: finalize -> scalar loss.
// ---------------------------------------------------------------------------
__global__ void k_final(float* __restrict__ out, int D,
                        const int* __restrict__ pptr) {
    __shared__ float wred[8];
    float part = 0.0f;
    for (int t = threadIdx.x; t < D; t += blockDim.x) {
        float v = g_total[t];
        part = fmaf(v, v, part);
    }
    #pragma unroll
    for (int o = 16; o > 0; o >>= 1)
        part += __shfl_down_sync(0xffffffffu, part, o);
    if ((threadIdx.x & 31) == 0) wred[threadIdx.x >> 5] = part;
    __syncthreads();
    if (threadIdx.x == 0) {
        float T2 = 0.0f;
        int nw = blockDim.x >> 5;
        for (int i = 0; i < nw; i++) T2 += wred[i];
        float Pf = (float)(*pptr);
        float S   = g_scalars[0];
        float son = g_scalars[1];
        float sc  = g_scalars[2];
        float within  = S - son;
        float between = Pf * sc - T2;
        float gpal    = sc / Pf - T2 / (Pf * Pf);
        out[0] = 0.1f * within / (between + 1e-6f) + 0.1f * gpal;
    }
}

// ---------------------------------------------------------------------------
extern "C" void kernel_launch(void* const* d_in, const int* in_sizes, int n_in,
                              void* d_out, int out_size) {
    const float* feat  = (const float*)d_in[0];
    const int*   ids32 = (const int*)d_in[1];   // stride-detected on device
    const int*   pptr  = (const int*)d_in[2];   // low 32 bits of num_patients
    (void)n_in; (void)out_size;

    int N = in_sizes[1];
    int D = in_sizes[0] / N;

    k_init<<<128, 256>>>(ids32, N, D, pptr);
    k_hist<<<1024, 256>>>(ids32, N, pptr);
    k_scan<<<1, 1024>>>();
    k_scatter<<<1024, 256>>>(ids32, N, pptr);
    k_patient<<<PMAX * SPLIT, TPB4>>>(feat, D, pptr);
    k_centroid<<<PMAX, 256>>>(D, pptr);
    k_final<<<1, 256>>>((float*)d_out, D, pptr);
}